// round 15
// baseline (speedup 1.0000x reference)
#include <cuda_runtime.h>

#define Bn 8
#define Cn 32
#define Hn 512
#define Wn 512
#define On 4
#define TW 64
#define TH 32
#define RR 4                    // output rows per thread
#define NROWS (RR + 2)          // loaded rows per thread (halo)
#define NTHREADS 256
#define BN_EPS 1e-5f
#define HW (Hn * Wn)

__device__ double g_stats[2 * On];   // [0..3] sum, [4..7] sumsq
__device__ float  g_scale[On];
__device__ float  g_bias[On];

__global__ void zero_stats_kernel() {
    if (threadIdx.x < 2 * On) g_stats[threadIdx.x] = 0.0;
}

// ---------------------------------------------------------------------------
// Pass 1: fused 5-tap stencil (4 directional diffs -> 1x1 conv 4C->4).
// Barrier-free engine: each lane owns 2 columns; horizontal neighbors come
// from warp shuffles; tile-edge columns from predicated halo loads in lanes
// 0/31. No smem staging, no per-channel barriers. Channel-ahead prefetch with
// manual A/B register double-buffering.
// ---------------------------------------------------------------------------
__global__ __launch_bounds__(NTHREADS, 2)
void fourdir_main(const float* __restrict__ x,
                  const float* __restrict__ wc_g,
                  float* __restrict__ out)
{
    __shared__ __align__(16) float swt[Cn][5][On];   // taps: NE,NW,SE,SW,C
    __shared__ float s_red[2 * On];

    const int tid = threadIdx.x;
    const int bxw = blockIdx.x;   // w tile (8)
    const int byh = blockIdx.y;   // h tile (16)
    const int bz  = blockIdx.z;   // batch (8)

    // Build combined weights once per block
    if (tid < Cn * On) {
        int c = tid >> 2, o = tid & 3;
        float w0 = wc_g[o * (4 * Cn) + 0 * Cn + c];  // NE
        float w1 = wc_g[o * (4 * Cn) + 1 * Cn + c];  // NW
        float w2 = wc_g[o * (4 * Cn) + 2 * Cn + c];  // SE
        float w3 = wc_g[o * (4 * Cn) + 3 * Cn + c];  // SW
        swt[c][0][o] = w0;
        swt[c][1][o] = w1;
        swt[c][2][o] = w2;
        swt[c][3][o] = w3;
        swt[c][4][o] = -(w0 + w1 + w2 + w3);         // center tap
    }
    if (tid < 2 * On) s_red[tid] = 0.0f;
    __syncthreads();   // weights + s_red visible (only barrier before epilogue)

    const int lane = tid & 31;
    const int g    = tid >> 5;            // warp id = row group
    const int cw   = bxw * TW + 2 * lane; // global col of this lane's even col
    const int rb   = byh * TH + g * RR;   // first output row (global)

    // per-row offsets & validity (reused across all channels)
    int  rowoff[NROWS];
    bool valid[NROWS];
#pragma unroll
    for (int r = 0; r < NROWS; ++r) {
        int lr = rb - 1 + r;
        valid[r]  = ((unsigned)lr < (unsigned)Hn);
        rowoff[r] = lr * Wn + cw;
    }
    // halo column: lane 0 loads cw-1 (left tile halo), lane 31 loads cw+2 (right)
    const bool hp   = (lane == 0) ? (bxw > 0) : ((lane == 31) ? (bxw < 7) : false);
    const int  hoff = (lane == 0) ? -1 : 2;

    const float* xb = x + (size_t)bz * Cn * HW;

    float2 vA[NROWS]; float hA[NROWS];
    float2 vB[NROWS]; float hB[NROWS];

    auto loadbuf = [&](float2 (&v)[NROWS], float (&h)[NROWS], const float* cp) {
#pragma unroll
        for (int r = 0; r < NROWS; ++r) {
            if (valid[r]) {
                v[r] = *(const float2*)(cp + rowoff[r]);
                h[r] = hp ? __ldg(cp + rowoff[r] + hoff) : 0.0f;
            } else {
                v[r] = make_float2(0.0f, 0.0f);
                h[r] = 0.0f;
            }
        }
    };

    float acc[RR][On][2];
#pragma unroll
    for (int i = 0; i < RR; ++i)
#pragma unroll
        for (int o = 0; o < On; ++o) { acc[i][o][0] = 0.0f; acc[i][o][1] = 0.0f; }

    auto compute = [&](const float2 (&v)[NROWS], const float (&h)[NROWS], int c) {
        float4 wNE = *(const float4*)&swt[c][0][0];
        float4 wNW = *(const float4*)&swt[c][1][0];
        float4 wSE = *(const float4*)&swt[c][2][0];
        float4 wSW = *(const float4*)&swt[c][3][0];
        float4 wCC = *(const float4*)&swt[c][4][0];
        const float* wne = &wNE.x;
        const float* wnw = &wNW.x;
        const float* wse = &wSE.x;
        const float* wsw = &wSW.x;
        const float* wcc = &wCC.x;

        float L[NROWS], R[NROWS];
#pragma unroll
        for (int r = 0; r < NROWS; ++r) {
            L[r] = __shfl_up_sync(0xffffffffu, v[r].y, 1);   // col cw-1
            if (lane == 0) L[r] = h[r];
            R[r] = __shfl_down_sync(0xffffffffu, v[r].x, 1); // col cw+2
            if (lane == 31) R[r] = h[r];
        }
#pragma unroll
        for (int i = 0; i < RR; ++i) {
            const int up = i, mid = i + 1, dn = i + 2;
#pragma unroll
            for (int o = 0; o < On; ++o) {
                // even col (w = cw): w+1 = v.y, w-1 = L, center = v[mid].x
                float a0 = acc[i][o][0];
                a0 += wne[o] * v[up].y;
                a0 += wnw[o] * L[up];
                a0 += wse[o] * v[dn].y;
                a0 += wsw[o] * L[dn];
                a0 += wcc[o] * v[mid].x;
                acc[i][o][0] = a0;
                // odd col (w = cw+1): w+1 = R, w-1 = v.x, center = v[mid].y
                float a1 = acc[i][o][1];
                a1 += wne[o] * R[up];
                a1 += wnw[o] * v[up].x;
                a1 += wse[o] * R[dn];
                a1 += wsw[o] * v[dn].x;
                a1 += wcc[o] * v[mid].y;
                acc[i][o][1] = a1;
            }
        }
    };

    // manual A/B double-buffered channel loop (channel-ahead prefetch)
    loadbuf(vA, hA, xb);                                   // channel 0
#pragma unroll 1
    for (int c = 0; c < Cn; c += 2) {
        loadbuf(vB, hB, xb + (size_t)(c + 1) * HW);        // prefetch c+1
        compute(vA, hA, c);
        const float* xn = xb + (size_t)((c + 2 < Cn) ? c + 2 : c) * HW;
        loadbuf(vA, hA, xn);                               // prefetch c+2
        compute(vB, hB, c + 1);
    }

    // epilogue: write y, accumulate BN stats
    float s[On] = {0, 0, 0, 0}, q[On] = {0, 0, 0, 0};
#pragma unroll
    for (int i = 0; i < RR; ++i) {
        int hrow = rb + i;
#pragma unroll
        for (int o = 0; o < On; ++o) {
            float2 y;
            y.x = acc[i][o][0];
            y.y = acc[i][o][1];
            *(float2*)(out + (((size_t)(bz * On + o)) * Hn + hrow) * Wn + cw) = y;
            s[o] += y.x + y.y;
            q[o] += y.x * y.x + y.y * y.y;
        }
    }
#pragma unroll
    for (int o = 0; o < On; ++o) {
        for (int offs = 16; offs; offs >>= 1) {
            s[o] += __shfl_xor_sync(0xffffffffu, s[o], offs);
            q[o] += __shfl_xor_sync(0xffffffffu, q[o], offs);
        }
    }
    if (lane == 0) {
#pragma unroll
        for (int o = 0; o < On; ++o) {
            atomicAdd(&s_red[o], s[o]);
            atomicAdd(&s_red[On + o], q[o]);
        }
    }
    __syncthreads();
    if (tid < 2 * On) atomicAdd(&g_stats[tid], (double)s_red[tid]);
}

// ---------------------------------------------------------------------------
// Pass 2: finalize BN scale/bias (tiny)
// ---------------------------------------------------------------------------
__global__ void finalize_stats(const float* __restrict__ gamma,
                               const float* __restrict__ beta)
{
    int o = threadIdx.x;
    if (o < On) {
        const double N = (double)Bn * Hn * Wn;
        double mean = g_stats[o] / N;
        double var  = g_stats[On + o] / N - mean * mean;
        float sc = gamma[o] * (float)(1.0 / sqrt(var + (double)BN_EPS));
        g_scale[o] = sc;
        g_bias[o]  = beta[o] - (float)mean * sc;
    }
}

// ---------------------------------------------------------------------------
// Pass 3: normalize d_out in place (proven ~11us form)
// ---------------------------------------------------------------------------
__global__ void apply_bn(float4* __restrict__ y)
{
    int i = blockIdx.x * blockDim.x + threadIdx.x;  // 2,097,152 float4s
    int c = (i >> 16) & 3;                          // 65536 float4 per (b,o) plane
    float sc = g_scale[c], bi = g_bias[c];
    float4 v = y[i];
    v.x = v.x * sc + bi;
    v.y = v.y * sc + bi;
    v.z = v.z * sc + bi;
    v.w = v.w * sc + bi;
    y[i] = v;
}

extern "C" void kernel_launch(void* const* d_in, const int* in_sizes, int n_in,
                              void* d_out, int out_size)
{
    const float* x     = (const float*)d_in[0];
    const float* w     = (const float*)d_in[1];
    const float* gamma = (const float*)d_in[2];
    const float* beta  = (const float*)d_in[3];
    float* out = (float*)d_out;

    zero_stats_kernel<<<1, 32>>>();

    dim3 grid(Wn / TW, Hn / TH, Bn);   // (8, 16, 8) = 1024 blocks
    fourdir_main<<<grid, NTHREADS>>>(x, w, out);

    finalize_stats<<<1, 32>>>(gamma, beta);

    int n4 = Bn * On * Hn * Wn / 4;    // 2,097,152 float4s
    apply_bn<<<n4 / 256, 256>>>((float4*)out);
}